// round 2
// baseline (speedup 1.0000x reference)
#include <cuda_runtime.h>
#include <math.h>

#define EPSQ 1e-8f

// Pre-normalized codebook scratch (K=1024, D=256)
__device__ float g_cbs[1024 * 256];

// ---------- packed f32x2 helpers (sm_103a: 2x FFMA throughput vs 3-reg FFMA) ----------
__device__ __forceinline__ unsigned long long pack2(float x, float y) {
    unsigned long long r;
    asm("mov.b64 %0, {%1, %2};" : "=l"(r) : "f"(x), "f"(y));
    return r;
}
__device__ __forceinline__ void fma2(unsigned long long& a, unsigned long long x, unsigned long long y) {
    asm("fma.rn.f32x2 %0, %1, %2, %0;" : "+l"(a) : "l"(x), "l"(y));
}
__device__ __forceinline__ float2 unpack2(unsigned long long v) {
    float2 r;
    asm("mov.b64 {%0, %1}, %2;" : "=f"(r.x), "=f"(r.y) : "l"(v));
    return r;
}
// ---------- cp.async helpers ----------
__device__ __forceinline__ void cp16(void* smem_dst, const void* gsrc) {
    unsigned sa = (unsigned)__cvta_generic_to_shared(smem_dst);
    asm volatile("cp.async.cg.shared.global [%0], [%1], 16;" :: "r"(sa), "l"(gsrc));
}
__device__ __forceinline__ void cp_commit() { asm volatile("cp.async.commit_group;"); }
template <int Np>
__device__ __forceinline__ void cp_wait() { asm volatile("cp.async.wait_group %0;" :: "n"(Np)); }

// ---------- kernel 1: codebook row norms + prescale ----------
__global__ void scale_codebook_kernel(const float* __restrict__ cb, int K) {
    int row = blockIdx.x * 8 + (threadIdx.x >> 5);
    int lane = threadIdx.x & 31;
    if (row >= K) return;
    const float4* src = (const float4*)(cb + (size_t)row * 256);
    float4 v0 = src[lane * 2];
    float4 v1 = src[lane * 2 + 1];
    float ss = v0.x * v0.x + v0.y * v0.y + v0.z * v0.z + v0.w * v0.w +
               v1.x * v1.x + v1.y * v1.y + v1.z * v1.z + v1.w * v1.w;
#pragma unroll
    for (int off = 16; off; off >>= 1) ss += __shfl_xor_sync(0xffffffffu, ss, off);
    float inv = 1.0f / fmaxf(sqrtf(ss), EPSQ);
    float4* dst = (float4*)(g_cbs + (size_t)row * 256);
    v0.x *= inv; v0.y *= inv; v0.z *= inv; v0.w *= inv;
    v1.x *= inv; v1.y *= inv; v1.z *= inv; v1.w *= inv;
    dst[lane * 2] = v0;
    dst[lane * 2 + 1] = v1;
}

// ---------- kernel 2: fused GEMM + gumbel + argmax + gather ----------
// 64 rows per block, K in chunks of 64, D=256 resident.
// smem stride 260 floats (65 float4): conflict-free LDS.128 phases.
#define STRF 260
#define STR4 65

__device__ __forceinline__ void load_B_chunk(float* Bsbuf, int kbase, int tid) {
#pragma unroll
    for (int t = 0; t < 16; t++) {
        int fid = tid + t * 256;
        int c = fid >> 6, d4 = fid & 63;
        cp16(Bsbuf + c * STRF + d4 * 4, g_cbs + ((size_t)(kbase + c)) * 256 + d4 * 4);
    }
}

__global__ void __launch_bounds__(256, 1)
quant_main_kernel(const float* __restrict__ latent, const float* __restrict__ noise,
                  const float* __restrict__ cb, const float* __restrict__ tptr,
                  float* __restrict__ out, int N, int K) {
    extern __shared__ float sm[];
    float* As = sm;                 // 64 x 260
    float* Bs = sm + 64 * STRF;     // 2 x 64 x 260
    __shared__ float s_scale[64];
    __shared__ int s_bestk[64];
    __shared__ float s_part[256];

    int tid = threadIdx.x;
    int tx = tid & 15, ty = tid >> 4;
    int rowbase = blockIdx.x * 64;

    // Issue latent tile loads (group 0)
#pragma unroll
    for (int t = 0; t < 16; t++) {
        int fid = tid + t * 256;
        int r = fid >> 6, d4 = fid & 63;
        cp16(As + r * STRF + d4 * 4, latent + ((size_t)(rowbase + r)) * 256 + d4 * 4);
    }
    cp_commit();
    // Issue B chunk 0 (group 1)
    load_B_chunk(Bs, 0, tid);
    cp_commit();

    cp_wait<1>();  // latent tile ready (chunk 0 may still be in flight)
    __syncthreads();

    // Row norms -> per-row scale 1/(max(||l||,eps)*temp)
    {
        int r = tid >> 2, seg = tid & 3;
        const float4* A4 = (const float4*)As;
        float ss = 0.0f;
#pragma unroll
        for (int q = 0; q < 16; q++) {
            float4 v = A4[r * STR4 + seg * 16 + q];
            ss += v.x * v.x + v.y * v.y + v.z * v.z + v.w * v.w;
        }
        s_part[tid] = ss;
    }
    __syncthreads();
    if (tid < 64) {
        float ss = s_part[tid * 4] + s_part[tid * 4 + 1] + s_part[tid * 4 + 2] + s_part[tid * 4 + 3];
        float tv = *tptr;
        s_scale[tid] = 1.0f / (fmaxf(sqrtf(ss), EPSQ) * tv);
    }
    __syncthreads();

    float sr[4];
#pragma unroll
    for (int i = 0; i < 4; i++) sr[i] = s_scale[ty + 16 * i];

    float bestv[4];
    int bestk[4];
#pragma unroll
    for (int i = 0; i < 4; i++) { bestv[i] = -__int_as_float(0x7f800000); bestk[i] = 0; }

    int nchunks = K >> 6;
    for (int c = 0; c < nchunks; c++) {
        int kbase = c << 6;
        if (c + 1 < nchunks) {
            load_B_chunk(Bs + ((c + 1) & 1) * 64 * STRF, kbase + 64, tid);
            cp_commit();
        }
        // Prefetch gumbel for this chunk (overlaps with cp.async wait)
        float g[4][4];
#pragma unroll
        for (int i = 0; i < 4; i++) {
#pragma unroll
            for (int j = 0; j < 4; j++) {
                float u = noise[(size_t)(rowbase + ty + 16 * i) * K + kbase + tx + 16 * j];
                g[i][j] = -logf(-logf(u));  // accurate logf: must track reference f32 chain
            }
        }
        if (c + 1 < nchunks) cp_wait<1>(); else cp_wait<0>();
        __syncthreads();

        const float4* A4 = (const float4*)As;
        const float4* B4 = (const float4*)(Bs + (c & 1) * 64 * STRF);
        const float4* ap[4];
        const float4* bp[4];
#pragma unroll
        for (int i = 0; i < 4; i++) ap[i] = A4 + (ty + 16 * i) * STR4;
#pragma unroll
        for (int j = 0; j < 4; j++) bp[j] = B4 + (tx + 16 * j) * STR4;

        unsigned long long acc[4][4][2];
#pragma unroll
        for (int i = 0; i < 4; i++)
#pragma unroll
            for (int j = 0; j < 4; j++) { acc[i][j][0] = 0ull; acc[i][j][1] = 0ull; }

#pragma unroll 4
        for (int d4 = 0; d4 < 64; ++d4) {
            unsigned long long al[4], ah[4], bl[4], bh[4];
#pragma unroll
            for (int i = 0; i < 4; i++) {
                float4 v = ap[i][d4];
                al[i] = pack2(v.x, v.y);
                ah[i] = pack2(v.z, v.w);
            }
#pragma unroll
            for (int j = 0; j < 4; j++) {
                float4 v = bp[j][d4];
                bl[j] = pack2(v.x, v.y);
                bh[j] = pack2(v.z, v.w);
            }
#pragma unroll
            for (int i = 0; i < 4; i++)
#pragma unroll
                for (int j = 0; j < 4; j++) {
                    fma2(acc[i][j][0], al[i], bl[j]);
                    fma2(acc[i][j][1], ah[i], bh[j]);
                }
        }

        // Epilogue: logits + running argmax (strict > keeps first max index)
#pragma unroll
        for (int i = 0; i < 4; i++) {
#pragma unroll
            for (int j = 0; j < 4; j++) {
                float2 p = unpack2(acc[i][j][0]);
                float2 q = unpack2(acc[i][j][1]);
                float dot = (p.x + p.y) + (q.x + q.y);
                float lg = dot * sr[i] + g[i][j];
                int kk = kbase + tx + 16 * j;
                if (lg > bestv[i]) { bestv[i] = lg; bestk[i] = kk; }
            }
        }
        __syncthreads();  // protect far B buffer before next-next refill
    }

    // Cross-thread argmax per row (16 lanes of a half-warp share a row)
#pragma unroll
    for (int i = 0; i < 4; i++) {
        float v = bestv[i];
        int k = bestk[i];
#pragma unroll
        for (int off = 8; off >= 1; off >>= 1) {
            float ov = __shfl_xor_sync(0xffffffffu, v, off);
            int ok = __shfl_xor_sync(0xffffffffu, k, off);
            if (ov > v || (ov == v && ok < k)) { v = ov; k = ok; }
        }
        if (tx == 0) s_bestk[ty + 16 * i] = k;
    }
    __syncthreads();

    // Gather winning codebook rows (original, unscaled codebook)
    const float4* cb4 = (const float4*)cb;
    float4* out4 = (float4*)out;
#pragma unroll
    for (int t = 0; t < 16; t++) {
        int fid = tid + t * 256;
        int r = fid >> 6, d4 = fid & 63;
        out4[((size_t)(rowbase + r)) * 64 + d4] = cb4[((size_t)s_bestk[r]) * 64 + d4];
    }
}

extern "C" void kernel_launch(void* const* d_in, const int* in_sizes, int n_in,
                              void* d_out, int out_size) {
    const float* latent = (const float*)d_in[0];
    const float* noise  = (const float*)d_in[1];
    const float* cb     = (const float*)d_in[2];
    const float* tptr   = (const float*)d_in[3];

    double s0 = (double)in_sizes[0], s1 = (double)in_sizes[1], s2 = (double)in_sizes[2];
    int D = (int)llround(sqrt(s0 * s2 / s1));   // 256
    int K = in_sizes[2] / D;                    // 1024
    int N = in_sizes[0] / D;                    // 131072

    scale_codebook_kernel<<<(K + 7) / 8, 256>>>(cb, K);

    size_t shmem = (size_t)(64 * STRF + 2 * 64 * STRF) * sizeof(float);  // ~195 KB
    cudaFuncSetAttribute(quant_main_kernel, cudaFuncAttributeMaxDynamicSharedMemorySize, (int)shmem);
    quant_main_kernel<<<N / 64, 256, shmem>>>(latent, noise, cb, tptr, (float*)d_out, N, K);
}

// round 4
// speedup vs baseline: 2.3389x; 2.3389x over previous
#include <cuda_runtime.h>
#include <cuda_fp16.h>
#include <math.h>
#include <stdint.h>

#define EPSQ 1e-8f

// fp16 2-way-split, row-normalized codebook (row-major [1024][256])
__device__ __half g_Bh[1024 * 256];
__device__ __half g_Bm[1024 * 256];

__device__ __forceinline__ uint32_t smem_u32(const void* p) {
    uint32_t a;
    asm("{ .reg .u64 t; cvta.to.shared.u64 t, %1; cvt.u32.u64 %0, t; }" : "=r"(a) : "l"(p));
    return a;
}
__device__ __forceinline__ void cp16(uint32_t smem_dst, const void* gsrc) {
    asm volatile("cp.async.cg.shared.global [%0], [%1], 16;" :: "r"(smem_dst), "l"(gsrc));
}
__device__ __forceinline__ void cp_commit() { asm volatile("cp.async.commit_group;"); }
template <int Np>
__device__ __forceinline__ void cp_wait() { asm volatile("cp.async.wait_group %0;" :: "n"(Np)); }

__device__ __forceinline__ void ldsm4(uint32_t* r, uint32_t addr) {
    asm volatile("ldmatrix.sync.aligned.m8n8.x4.shared.b16 {%0,%1,%2,%3}, [%4];"
                 : "=r"(r[0]), "=r"(r[1]), "=r"(r[2]), "=r"(r[3]) : "r"(addr));
}
__device__ __forceinline__ void mma16816(float* d, const uint32_t* a, const uint32_t* b) {
    asm volatile(
        "mma.sync.aligned.m16n8k16.row.col.f32.f16.f16.f32 "
        "{%0,%1,%2,%3},{%4,%5,%6,%7},{%8,%9},{%0,%1,%2,%3};"
        : "+f"(d[0]), "+f"(d[1]), "+f"(d[2]), "+f"(d[3])
        : "r"(a[0]), "r"(a[1]), "r"(a[2]), "r"(a[3]), "r"(b[0]), "r"(b[1]));
}

// ---- prep: normalize codebook rows, fp16 2-way split ----
__global__ void prep_codebook(const float* __restrict__ cb, int K) {
    int row = blockIdx.x * 8 + (threadIdx.x >> 5);
    int lane = threadIdx.x & 31;
    if (row >= K) return;
    const float4* src = (const float4*)(cb + (size_t)row * 256);
    float4 a = src[lane * 2], b = src[lane * 2 + 1];
    float ss = a.x*a.x + a.y*a.y + a.z*a.z + a.w*a.w + b.x*b.x + b.y*b.y + b.z*b.z + b.w*b.w;
#pragma unroll
    for (int off = 16; off; off >>= 1) ss += __shfl_xor_sync(0xffffffffu, ss, off);
    float inv = 1.0f / fmaxf(sqrtf(ss), EPSQ);
    float v[8] = {a.x, a.y, a.z, a.w, b.x, b.y, b.z, b.w};
#pragma unroll
    for (int q = 0; q < 8; q++) {
        int k = lane * 8 + q;
        float x = v[q] * inv;
        __half h = __float2half_rn(x);
        __half m = __float2half_rn(x - __half2float(h));
        g_Bh[(size_t)row * 256 + k] = h;
        g_Bm[(size_t)row * 256 + k] = m;
    }
}

// ---- main fused kernel ----
// smem: Ah 0..64K, Am 64K..128K, B 128K..192K (2 stages x (Bh 16K | Bm 16K))
// chunk = 32 codebook rows; 32 chunks. Warp grid 4(M) x 2(N); warp tile 32x16 x 2nt.
__global__ void __launch_bounds__(256, 1)
quant_mma(const float* __restrict__ latent, const float* __restrict__ noise,
          const float* __restrict__ cb, const float* __restrict__ tptr,
          float* __restrict__ out, int K) {
    extern __shared__ char dsm[];
    __shared__ float s_scale[128];
    __shared__ float s_bv[256];
    __shared__ int s_bk[256];
    __shared__ int s_win[128];

    const int tid = threadIdx.x, lane = tid & 31, wid = tid >> 5;
    const int wm = wid & 3, wn = wid >> 2;
    const int rowbase = blockIdx.x * 128;
    const uint32_t smA = smem_u32(dsm);
    const uint32_t smB = smA + 131072u;

    // issue B chunks 0,1
#pragma unroll
    for (int st = 0; st < 2; st++) {
#pragma unroll
        for (int i = 0; i < 4; i++) {
            int idx = tid + i * 256;
            int n = idx >> 5, c16 = idx & 31;
            uint32_t off = (uint32_t)(n * 512) + (uint32_t)((c16 * 16) ^ ((n & 7) << 4));
            const char* srcb = (const char*)g_Bh + ((size_t)(st * 32 + n) * 256 + c16 * 8) * 2;
            cp16(smB + st * 32768u + off, srcb);
            const char* srcm = (const char*)g_Bm + ((size_t)(st * 32 + n) * 256 + c16 * 8) * 2;
            cp16(smB + st * 32768u + 16384u + off, srcm);
        }
        cp_commit();
    }

    // A: load fp32, split to (h|m), swizzled STS; row norms
    {
        float tv = *tptr;
        int r = tid >> 1, h2 = tid & 1;
        const float4* ar = (const float4*)(latent + (size_t)(rowbase + r) * 256);
        uint32_t sw = (uint32_t)((r & 7) << 4);
        char* pAh = dsm + r * 512;
        char* pAm = pAh + 65536;
        float ss = 0.0f;
#pragma unroll
        for (int q = 0; q < 32; q++) {
            int d4 = h2 * 32 + q;
            float4 v = ar[d4];
            ss += v.x * v.x + v.y * v.y + v.z * v.z + v.w * v.w;
            __half h0 = __float2half_rn(v.x), h1 = __float2half_rn(v.y);
            __half h2a = __float2half_rn(v.z), h3 = __float2half_rn(v.w);
            __half m0 = __float2half_rn(v.x - __half2float(h0));
            __half m1 = __float2half_rn(v.y - __half2float(h1));
            __half m2 = __float2half_rn(v.z - __half2float(h2a));
            __half m3 = __float2half_rn(v.w - __half2float(h3));
            uint2 hp, mp;
            hp.x = (uint32_t)__half_as_ushort(h0) | ((uint32_t)__half_as_ushort(h1) << 16);
            hp.y = (uint32_t)__half_as_ushort(h2a) | ((uint32_t)__half_as_ushort(h3) << 16);
            mp.x = (uint32_t)__half_as_ushort(m0) | ((uint32_t)__half_as_ushort(m1) << 16);
            mp.y = (uint32_t)__half_as_ushort(m2) | ((uint32_t)__half_as_ushort(m3) << 16);
            uint32_t off = (uint32_t)(d4 * 8) ^ sw;
            *(uint2*)(pAh + off) = hp;
            *(uint2*)(pAm + off) = mp;
        }
        ss += __shfl_xor_sync(0xffffffffu, ss, 1);
        if (h2 == 0) s_scale[r] = 1.0f / (fmaxf(sqrtf(ss), EPSQ) * tv);
    }
    __syncthreads();

    // fragment address constants
    const int m8 = lane >> 3, rl = lane & 7;
    const uint32_t sw = (uint32_t)(rl << 4);
    const uint32_t aBase0 = smA + (uint32_t)((wm * 32 + rl + 8 * (m8 & 1)) * 512);
    const uint32_t aBase1 = aBase0 + 16 * 512;
    const uint32_t aKoff = (uint32_t)((m8 >> 1) * 16);
    const uint32_t bRow = (uint32_t)((wn * 16 + (m8 >> 1) * 8 + rl) * 512);
    const uint32_t bKoff = (uint32_t)((m8 & 1) * 16);

    // epilogue constants: 4 owned rows
    const int eR = wm * 32 + (lane >> 2);
    const float* nrow[4];
    float sc[4];
    float best[4];
    int bk[4];
#pragma unroll
    for (int ri = 0; ri < 4; ri++) {
        int R = eR + (ri & 1) * 8 + (ri >> 1) * 16;
        nrow[ri] = noise + (size_t)(rowbase + R) * K;
        sc[ri] = s_scale[R];
        best[ri] = -__int_as_float(0x7f800000);
        bk[ri] = 0;
    }

    for (int c = 0; c < 32; c++) {
        // gumbel prefetch for this chunk
        int cb0 = c * 32 + wn * 16 + (lane & 3) * 2;
        float2 u[4][2];
#pragma unroll
        for (int ri = 0; ri < 4; ri++) {
            u[ri][0] = *(const float2*)(nrow[ri] + cb0);
            u[ri][1] = *(const float2*)(nrow[ri] + cb0 + 8);
        }
        if (c < 31) cp_wait<1>(); else cp_wait<0>();
        __syncthreads();

        const uint32_t Bst = smB + (uint32_t)((c & 1) * 32768);
        float acc[2][2][4];
#pragma unroll
        for (int i = 0; i < 2; i++)
#pragma unroll
            for (int j = 0; j < 2; j++)
#pragma unroll
                for (int q = 0; q < 4; q++) acc[i][j][q] = 0.0f;

#pragma unroll
        for (int ks = 0; ks < 16; ks++) {
            uint32_t offA = ((uint32_t)(ks * 32) + aKoff) ^ sw;
            uint32_t offB = ((uint32_t)(ks * 32) + bKoff) ^ sw;
            uint32_t bh[4], bm[4], ah0[4], ah1[4], am0[4], am1[4];
            ldsm4(bh, Bst + bRow + offB);
            ldsm4(bm, Bst + 16384u + bRow + offB);
            ldsm4(ah0, aBase0 + offA);
            ldsm4(ah1, aBase1 + offA);
            ldsm4(am0, aBase0 + 65536u + offA);
            ldsm4(am1, aBase1 + 65536u + offA);
#pragma unroll
            for (int nt = 0; nt < 2; nt++) {
                mma16816(acc[0][nt], ah0, bh + 2 * nt);
                mma16816(acc[1][nt], ah1, bh + 2 * nt);
                mma16816(acc[0][nt], am0, bh + 2 * nt);
                mma16816(acc[1][nt], am1, bh + 2 * nt);
                mma16816(acc[0][nt], ah0, bm + 2 * nt);
                mma16816(acc[1][nt], ah1, bm + 2 * nt);
            }
        }

        // fused epilogue: scale + gumbel + running argmax
#pragma unroll
        for (int mt = 0; mt < 2; mt++)
#pragma unroll
            for (int nt = 0; nt < 2; nt++)
#pragma unroll
                for (int hi = 0; hi < 2; hi++) {
                    int ri = mt * 2 + hi;
                    float2 uu = u[ri][nt];
                    float g0 = -logf(-logf(uu.x));
                    float g1 = -logf(-logf(uu.y));
                    float l0 = fmaf(acc[mt][nt][hi * 2 + 0], sc[ri], g0);
                    float l1 = fmaf(acc[mt][nt][hi * 2 + 1], sc[ri], g1);
                    int c0 = cb0 + nt * 8;
                    if (l0 > best[ri]) { best[ri] = l0; bk[ri] = c0; }
                    if (l1 > best[ri]) { best[ri] = l1; bk[ri] = c0 + 1; }
                }
        __syncthreads();

        if (c + 2 < 32) {
            int nc = c + 2;
            uint32_t stb = smB + (uint32_t)((nc & 1) * 32768);
#pragma unroll
            for (int i = 0; i < 4; i++) {
                int idx = tid + i * 256;
                int n = idx >> 5, c16 = idx & 31;
                uint32_t off = (uint32_t)(n * 512) + (uint32_t)((c16 * 16) ^ ((n & 7) << 4));
                const char* srcb = (const char*)g_Bh + ((size_t)(nc * 32 + n) * 256 + c16 * 8) * 2;
                cp16(stb + off, srcb);
                const char* srcm = (const char*)g_Bm + ((size_t)(nc * 32 + n) * 256 + c16 * 8) * 2;
                cp16(stb + 16384u + off, srcm);
            }
            cp_commit();
        }
    }

    // reduce across quad lanes (strict >, ties -> smaller k)
#pragma unroll
    for (int ri = 0; ri < 4; ri++) {
        float v = best[ri];
        int k = bk[ri];
#pragma unroll
        for (int off = 1; off <= 2; off <<= 1) {
            float ov = __shfl_xor_sync(0xffffffffu, v, off);
            int ok = __shfl_xor_sync(0xffffffffu, k, off);
            if (ov > v || (ov == v && ok < k)) { v = ov; k = ok; }
        }
        if ((lane & 3) == 0) {
            int R = eR + (ri & 1) * 8 + (ri >> 1) * 16;
            s_bv[R * 2 + wn] = v;
            s_bk[R * 2 + wn] = k;
        }
    }
    __syncthreads();
    if (tid < 128) {
        float v0 = s_bv[tid * 2], v1 = s_bv[tid * 2 + 1];
        int k0 = s_bk[tid * 2], k1 = s_bk[tid * 2 + 1];
        s_win[tid] = (v1 > v0 || (v1 == v0 && k1 < k0)) ? k1 : k0;
    }
    __syncthreads();

    // gather winning codebook rows (original fp32 codebook)
    const float4* cb4 = (const float4*)cb;
    float4* o4 = (float4*)out;
#pragma unroll
    for (int t = 0; t < 32; t++) {
        int idx = tid + t * 256;
        int r = idx >> 6, d4 = idx & 63;
        o4[(size_t)(rowbase + r) * 64 + d4] = cb4[(size_t)s_win[r] * 64 + d4];
    }
}

extern "C" void kernel_launch(void* const* d_in, const int* in_sizes, int n_in,
                              void* d_out, int out_size) {
    const float* latent = (const float*)d_in[0];
    const float* noise  = (const float*)d_in[1];
    const float* cb     = (const float*)d_in[2];
    const float* tptr   = (const float*)d_in[3];

    double s0 = (double)in_sizes[0], s1 = (double)in_sizes[1], s2 = (double)in_sizes[2];
    int D = (int)llround(sqrt(s0 * s2 / s1));   // 256
    int K = in_sizes[2] / D;                    // 1024
    int N = in_sizes[0] / D;                    // 131072

    prep_codebook<<<K / 8, 256>>>(cb, K);

    int shm = 196608;  // 192 KB
    cudaFuncSetAttribute(quant_mma, cudaFuncAttributeMaxDynamicSharedMemorySize, shm);
    quant_mma<<<N / 128, 256, shm>>>(latent, noise, cb, tptr, (float*)d_out, K);
}